// round 8
// baseline (speedup 1.0000x reference)
#include <cuda_runtime.h>
#include <cstdint>

// OuterProductMean — mma.sync tf32, fused, 2 CTAs/SM (16-pair CTA tiles).
//
//  ln_wo  : blocks 0..255: LayerNorm + dual projection (2 blocks per s)
//           blocks 256..287: g_wo32 = tf32(rna)-rounded wo
//  fused  : per CTA (i-block 4, j-block 4):
//    phase1: o[128 (i,c)][128 (j,d)] = sum_s a*b  (mma tf32, K=128 in 2 halves)
//    stage o -> Os[k2=1024][16] (bank-skewed, stride 16, no pad)
//    phase2: Z[16 pairs][128 z] = Os * wo^T (K=1024, 32-k2 cp.async chunks,
//            2-way k-split + cross-warp reduction)

#define S_DIM 128
#define R_DIM 256
#define CM    256
#define CC    32
#define CZ    128
#define MDIM  (R_DIM * CC)          // 8192

__device__ float g_a[(size_t)S_DIM * MDIM];     // 4 MB  [s][m]
__device__ float g_b[(size_t)S_DIM * MDIM];     // 4 MB  [s][n]
__device__ float g_wo32[(size_t)CZ * CC * CC];  // 512 KB [z][k2]

// ---------------------------------------------------------------- helpers
__device__ __forceinline__ uint32_t su32(const void* p) {
    uint32_t a;
    asm("{ .reg .u64 t; cvta.to.shared.u64 t, %1; cvt.u32.u64 %0, t; }"
        : "=r"(a) : "l"(p));
    return a;
}
__device__ __forceinline__ uint32_t tf32r(float f) {
    uint32_t r;
    asm("cvt.rna.tf32.f32 %0, %1;" : "=r"(r) : "f"(f));
    return r;
}
__device__ __forceinline__ float tf32f(float f) { return __uint_as_float(tf32r(f)); }

__device__ __forceinline__ void cp16(void* dst_smem, const void* src) {
    asm volatile("cp.async.cg.shared.global [%0], [%1], 16;"
                 :: "r"(su32(dst_smem)), "l"(src));
}
__device__ __forceinline__ void cp_commit() {
    asm volatile("cp.async.commit_group;" ::: "memory");
}
template <int N>
__device__ __forceinline__ void cp_wait() {
    asm volatile("cp.async.wait_group %0;" :: "n"(N) : "memory");
}

// D(16x8) += A(16x8 row) * B(8x8 col), tf32
__device__ __forceinline__ void mma8(float* d, const uint32_t* a, uint32_t b0, uint32_t b1) {
    asm volatile(
        "mma.sync.aligned.m16n8k8.row.col.f32.tf32.tf32.f32 "
        "{%0,%1,%2,%3}, {%4,%5,%6,%7}, {%8,%9}, {%0,%1,%2,%3};"
        : "+f"(d[0]), "+f"(d[1]), "+f"(d[2]), "+f"(d[3])
        : "r"(a[0]), "r"(a[1]), "r"(a[2]), "r"(a[3]), "r"(b0), "r"(b1));
}

// ---------------------------------------------------------------- ln + proj (+ wo convert)
#define LN_STRIDE 264
#define LN_SMEM ((64 + 32) * LN_STRIDE * 4)

__global__ __launch_bounds__(256, 1)
void ln_wo_kernel(const float* __restrict__ m,
                  const float* __restrict__ ln_w, const float* __restrict__ ln_b,
                  const float* __restrict__ w1, const float* __restrict__ b1,
                  const float* __restrict__ w2, const float* __restrict__ b2,
                  const float* __restrict__ wo) {
    // blocks 256..287: tf32-round wo (32 blocks * 256 thr * 16 elems = 131072)
    if (blockIdx.x >= 2 * S_DIM) {
        const int base = ((blockIdx.x - 2 * S_DIM) * 256 + threadIdx.x) * 16;
        #pragma unroll
        for (int t = 0; t < 4; t++) {
            const float4 v = *(const float4*)&wo[base + 4 * t];
            float4 r; r.x = tf32f(v.x); r.y = tf32f(v.y); r.z = tf32f(v.z); r.w = tf32f(v.w);
            *(float4*)&g_wo32[base + 4 * t] = r;
        }
        return;
    }

    extern __shared__ __align__(16) float sm_[];
    float* ws = sm_;                     // [64][264]: w1 rows 0..31, w2 rows 32..63
    float* xs = sm_ + 64 * LN_STRIDE;    // [32][264] normalized rows

    const int s = blockIdx.x >> 1;
    const int half = blockIdx.x & 1;
    const int tid = threadIdx.x, w = tid >> 5, lane = tid & 31;

    for (int idx = tid; idx < 64 * 64; idx += 256) {
        const int row = idx >> 6, k4 = idx & 63;
        const float* src = (row < 32) ? (w1 + (size_t)row * CM)
                                      : (w2 + (size_t)(row - 32) * CM);
        *(float4*)(ws + row * LN_STRIDE + k4 * 4) = *(const float4*)(src + k4 * 4);
    }

    const float4 lw0 = ((const float4*)ln_w)[lane], lw1 = ((const float4*)ln_w)[lane + 32];
    const float4 lb0 = ((const float4*)ln_b)[lane], lb1 = ((const float4*)ln_b)[lane + 32];

    const int o0 = (tid >> 3) * 2, r0 = tid & 7;
    const float bias0 = (o0 < 32) ? b1[o0] : b2[o0 - 32];
    const float bias1 = (o0 < 32) ? b1[o0 + 1] : b2[o0 + 1 - 32];

    for (int b0r = half * 128; b0r < half * 128 + 128; b0r += 32) {
        __syncthreads();   // ws loaded / previous GEMM done reading xs
        #pragma unroll
        for (int p = 0; p < 4; p++) {
            const int r = p * 8 + w;
            const float* rowp = m + ((size_t)s * R_DIM + (b0r + r)) * CM;
            const float4 v0 = ((const float4*)rowp)[lane];
            const float4 v1 = ((const float4*)rowp)[lane + 32];
            float sum = v0.x + v0.y + v0.z + v0.w + v1.x + v1.y + v1.z + v1.w;
            #pragma unroll
            for (int o = 16; o; o >>= 1) sum += __shfl_xor_sync(~0u, sum, o);
            const float mu = sum * (1.0f / CM);
            const float d0 = v0.x - mu, d1 = v0.y - mu, d2 = v0.z - mu, d3 = v0.w - mu;
            const float d4 = v1.x - mu, d5 = v1.y - mu, d6 = v1.z - mu, d7 = v1.w - mu;
            float vs = d0*d0 + d1*d1 + d2*d2 + d3*d3 + d4*d4 + d5*d5 + d6*d6 + d7*d7;
            #pragma unroll
            for (int o = 16; o; o >>= 1) vs += __shfl_xor_sync(~0u, vs, o);
            const float rstd = rsqrtf(vs * (1.0f / CM) + 1e-5f);
            float4 y0, y1;
            y0.x = d0 * rstd * lw0.x + lb0.x;  y0.y = d1 * rstd * lw0.y + lb0.y;
            y0.z = d2 * rstd * lw0.z + lb0.z;  y0.w = d3 * rstd * lw0.w + lb0.w;
            y1.x = d4 * rstd * lw1.x + lb1.x;  y1.y = d5 * rstd * lw1.y + lb1.y;
            y1.z = d6 * rstd * lw1.z + lb1.z;  y1.w = d7 * rstd * lw1.w + lb1.w;
            *(float4*)(xs + r * LN_STRIDE + 4 * lane)       = y0;
            *(float4*)(xs + r * LN_STRIDE + 128 + 4 * lane) = y1;
        }
        __syncthreads();

        float acc0[4] = {0.f, 0.f, 0.f, 0.f}, acc1[4] = {0.f, 0.f, 0.f, 0.f};
        const float* wr0 = ws + o0 * LN_STRIDE;
        const float* wr1 = wr0 + LN_STRIDE;
        #pragma unroll 8
        for (int k4 = 0; k4 < 64; k4++) {
            const float4 wa = *(const float4*)(wr0 + k4 * 4);
            const float4 wb = *(const float4*)(wr1 + k4 * 4);
            #pragma unroll
            for (int u = 0; u < 4; u++) {
                const float4 x = *(const float4*)(xs + (r0 + 8 * u) * LN_STRIDE + k4 * 4);
                acc0[u] = fmaf(wa.x, x.x, acc0[u]); acc0[u] = fmaf(wa.y, x.y, acc0[u]);
                acc0[u] = fmaf(wa.z, x.z, acc0[u]); acc0[u] = fmaf(wa.w, x.w, acc0[u]);
                acc1[u] = fmaf(wb.x, x.x, acc1[u]); acc1[u] = fmaf(wb.y, x.y, acc1[u]);
                acc1[u] = fmaf(wb.z, x.z, acc1[u]); acc1[u] = fmaf(wb.w, x.w, acc1[u]);
            }
        }
        #pragma unroll
        for (int u = 0; u < 4; u++) {
            const int i_abs = b0r + r0 + 8 * u;
            float2 v;
            v.x = acc0[u] + bias0;
            v.y = acc1[u] + bias1;
            if (o0 < 32)
                *(float2*)&g_a[(size_t)s * MDIM + i_abs * CC + o0] = v;
            else
                *(float2*)&g_b[(size_t)s * MDIM + i_abs * CC + (o0 - 32)] = v;
        }
    }
}

// ---------------------------------------------------------------- fused
// SMEM (floats), total 26624 fl = 106496 B  -> 2 CTAs/SM:
//   phase1: sA[64][136] (8704) + sB[64][136] (8704) at offset 0   (K-halved)
//   phase2: Os[1024][16] (16384) reuses offset 0  (skew-addressed, no pad)
//   wo bufs: 2 x [128][36] (2x4608) at offset 17408  (disjoint from phase1)
//   reduction scratch (2048 fl) reuses wo-buffer region.
#define SAB_STRIDE 136
#define SB_OFF     (64 * SAB_STRIDE)       // 8704
#define WO_OFF     (2 * 64 * SAB_STRIDE)   // 17408
#define WO_BUF     (128 * 36)              // 4608
#define FUSED_SMEM ((WO_OFF + 2 * WO_BUF) * 4)   // 106496 B

// Os addressing: value (k2, col p in 0..15) at  k2*16 + ((p + 4*(k2&3) + (k2>>5)) & 15)

__device__ __forceinline__ void issue_wo(float* buf, int cc, int tid) {
    // chunk cc: g_wo32[z][cc*32 .. +31], 128 z x 32 k2 = 1024 cp16, 2 per thread
    #pragma unroll
    for (int t = 0; t < 2; t++) {
        const int idx = tid + t * 512;
        const int z = idx >> 3, q = idx & 7;
        cp16(buf + z * 36 + 4 * q, g_wo32 + (size_t)z * 1024 + cc * 32 + 4 * q);
    }
}

__global__ __launch_bounds__(512, 2)
void fused_kernel(const float* __restrict__ bo, float* __restrict__ out) {
    extern __shared__ __align__(16) float sm[];
    const int tid = threadIdx.x, w = tid >> 5, lane = tid & 31;
    const int g = lane >> 2, tg = lane & 3;
    const int i0 = blockIdx.x * 4, j0 = blockIdx.y * 4;
    const int m0 = i0 * CC, n0 = j0 * CC;

    float* wob0 = sm + WO_OFF;
    float* wob1 = sm + WO_OFF + WO_BUF;
    // prefetch wo chunks 0/1 immediately (region disjoint from phase-1 tiles)
    issue_wo(wob0, 0, tid); cp_commit();
    issue_wo(wob1, 1, tid); cp_commit();

    // ---- phase 1: o[128 (i,c)][128 (j,d)] = A * B^T over k=128 (2 halves) ----
    const int mr = w >> 2, nc = w & 3;          // 4x4 warp grid, 32m x 32n tiles
    const int mA = 32 * mr + g;
    const int nB = 32 * nc + g;

    float acc[2][4][4];
    #pragma unroll
    for (int mt = 0; mt < 2; mt++)
        #pragma unroll
        for (int nt = 0; nt < 4; nt++)
            #pragma unroll
            for (int q = 0; q < 4; q++) acc[mt][nt][q] = 0.f;

    #pragma unroll
    for (int kh = 0; kh < 2; kh++) {
        if (kh) __syncthreads();                // previous compute done before reload
        for (int idx = tid; idx < 64 * 32; idx += 512) {
            const int k = idx >> 5, q = idx & 31;
            const float4 va = *(const float4*)&g_a[(size_t)(kh * 64 + k) * MDIM + m0 + 4 * q];
            float4 ra; ra.x = tf32f(va.x); ra.y = tf32f(va.y); ra.z = tf32f(va.z); ra.w = tf32f(va.w);
            *(float4*)&sm[k * SAB_STRIDE + 4 * q] = ra;
            const float4 vb = *(const float4*)&g_b[(size_t)(kh * 64 + k) * MDIM + n0 + 4 * q];
            float4 rb; rb.x = tf32f(vb.x); rb.y = tf32f(vb.y); rb.z = tf32f(vb.z); rb.w = tf32f(vb.w);
            *(float4*)&sm[SB_OFF + k * SAB_STRIDE + 4 * q] = rb;
        }
        __syncthreads();

        #pragma unroll
        for (int ks = 0; ks < 8; ks++) {
            const int k0 = ks * 8;
            uint32_t a[2][4];
            #pragma unroll
            for (int mt = 0; mt < 2; mt++) {
                const int mb = mA + 16 * mt;
                a[mt][0] = __float_as_uint(sm[(k0 + tg)     * SAB_STRIDE + mb]);
                a[mt][1] = __float_as_uint(sm[(k0 + tg)     * SAB_STRIDE + mb + 8]);
                a[mt][2] = __float_as_uint(sm[(k0 + tg + 4) * SAB_STRIDE + mb]);
                a[mt][3] = __float_as_uint(sm[(k0 + tg + 4) * SAB_STRIDE + mb + 8]);
            }
            #pragma unroll
            for (int nt = 0; nt < 4; nt++) {
                const uint32_t b0 = __float_as_uint(sm[SB_OFF + (k0 + tg)     * SAB_STRIDE + nB + 8 * nt]);
                const uint32_t b1 = __float_as_uint(sm[SB_OFF + (k0 + tg + 4) * SAB_STRIDE + nB + 8 * nt]);
                mma8(acc[0][nt], a[0], b0, b1);
                mma8(acc[1][nt], a[1], b0, b1);
            }
        }
    }
    __syncthreads();   // all warps done reading sA/sB; safe to overwrite with Os

    // ---- stage o -> Os (skew-addressed, stride 16) ----
    float* Os = sm;
    const int p1 = mr * 4 + nc;                 // this warp's (i_l, j_l) pair
    #pragma unroll
    for (int mt = 0; mt < 2; mt++) {
        #pragma unroll
        for (int nt = 0; nt < 4; nt++) {
            const int d = 8 * nt + 2 * tg;
            #pragma unroll
            for (int rr = 0; rr < 2; rr++) {
                const int c = 16 * mt + 8 * rr + g;
                const int k2a = c * 32 + d, k2b = k2a + 1;
                Os[k2a * 16 + ((p1 + 4 * (k2a & 3) + c) & 15)] = tf32f(acc[mt][nt][2 * rr]);
                Os[k2b * 16 + ((p1 + 4 * (k2b & 3) + c) & 15)] = tf32f(acc[mt][nt][2 * rr + 1]);
            }
        }
    }

    // ---- phase 2: Z[16][128] = Os * wo^T over k2=1024, 32 chunks of 32 ----
    const int kg = w >> 3, zg = w & 7;          // k-half x z-group(16)
    float zacc[2][4];
    #pragma unroll
    for (int nt = 0; nt < 2; nt++)
        #pragma unroll
        for (int q = 0; q < 4; q++) zacc[nt][q] = 0.f;

    for (int cc = 0; cc < 32; cc++) {
        cp_wait<1>();
        __syncthreads();                        // chunk cc ready; Os visible (cc=0)
        const float* W = (cc & 1) ? wob1 : wob0;
        #pragma unroll
        for (int ks2 = 0; ks2 < 2; ks2++) {
            const int ks = kg * 2 + ks2;        // 0..3 within chunk
            const int k2 = cc * 32 + ks * 8;
            const int ch = k2 >> 5;
            uint32_t a[4];
            // rows k2+tg and k2+4+tg; (row&3)==tg for both; skew = 4*tg + ch
            const int sk = (4 * tg + ch);
            a[0] = __float_as_uint(Os[(k2 + tg)     * 16 + ((g     + sk) & 15)]);
            a[1] = __float_as_uint(Os[(k2 + tg)     * 16 + ((g + 8 + sk) & 15)]);
            a[2] = __float_as_uint(Os[(k2 + 4 + tg) * 16 + ((g     + sk) & 15)]);
            a[3] = __float_as_uint(Os[(k2 + 4 + tg) * 16 + ((g + 8 + sk) & 15)]);
            const int kc = ks * 8;
            #pragma unroll
            for (int nt = 0; nt < 2; nt++) {
                const int zz = 16 * zg + 8 * nt + g;
                const uint32_t b0 = __float_as_uint(W[zz * 36 + kc + tg]);
                const uint32_t b1 = __float_as_uint(W[zz * 36 + kc + tg + 4]);
                mma8(zacc[nt], a, b0, b1);
            }
        }
        __syncthreads();                        // all warps done with this buffer
        if (cc + 2 < 32) issue_wo((cc & 1) ? wob1 : wob0, cc + 2, tid);
        cp_commit();                            // unconditional: keeps wait<1> math valid
    }

    // ---- cross-k-half reduction (kg=1 -> scratch, kg=0 adds) ----
    float* scratch = sm + WO_OFF;               // 8*32*8 = 2048 fl
    if (kg == 1) {
        float* dst = scratch + ((zg * 32 + lane) << 3);
        #pragma unroll
        for (int nt = 0; nt < 2; nt++)
            *(float4*)&dst[nt * 4] = *(float4*)&zacc[nt][0];
    }
    __syncthreads();
    if (kg == 0) {
        const float* src = scratch + ((zg * 32 + lane) << 3);
        #pragma unroll
        for (int nt = 0; nt < 2; nt++) {
            const float4 v = *(const float4*)&src[nt * 4];
            zacc[nt][0] += v.x; zacc[nt][1] += v.y;
            zacc[nt][2] += v.z; zacc[nt][3] += v.w;
        }
        // ---- epilogue ----
        #pragma unroll
        for (int nt = 0; nt < 2; nt++) {
            const int zz = 16 * zg + 8 * nt + 2 * tg;
            const float2 bo2 = *(const float2*)&bo[zz];
            #pragma unroll
            for (int rr = 0; rr < 2; rr++) {
                const int p = g + 8 * rr;
                const int i = i0 + (p >> 2), j = j0 + (p & 3);
                float2 v;
                v.x = (zacc[nt][2 * rr + 0] + bo2.x) * (1.0f / S_DIM);
                v.y = (zacc[nt][2 * rr + 1] + bo2.y) * (1.0f / S_DIM);
                *(float2*)&out[((size_t)i * R_DIM + j) * CZ + zz] = v;
            }
        }
    }
}

// ---------------------------------------------------------------- launch
extern "C" void kernel_launch(void* const* d_in, const int* in_sizes, int n_in,
                              void* d_out, int out_size) {
    const float* m    = (const float*)d_in[0];
    const float* ln_w = (const float*)d_in[1];
    const float* ln_b = (const float*)d_in[2];
    const float* w1   = (const float*)d_in[3];
    const float* b1   = (const float*)d_in[4];
    const float* w2   = (const float*)d_in[5];
    const float* b2   = (const float*)d_in[6];
    const float* wo   = (const float*)d_in[7];
    const float* bo   = (const float*)d_in[8];
    float* out = (float*)d_out;

    cudaFuncSetAttribute(ln_wo_kernel, cudaFuncAttributeMaxDynamicSharedMemorySize, LN_SMEM);
    cudaFuncSetAttribute(fused_kernel, cudaFuncAttributeMaxDynamicSharedMemorySize, FUSED_SMEM);

    ln_wo_kernel<<<2 * S_DIM + 32, 256, LN_SMEM>>>(m, ln_w, ln_b, w1, b1, w2, b2, wo);
    fused_kernel<<<dim3(R_DIM / 4, R_DIM / 4), 512, FUSED_SMEM>>>(bo, out);
}

// round 9
// speedup vs baseline: 1.4111x; 1.4111x over previous
#include <cuda_runtime.h>
#include <cuda_fp16.h>
#include <cstdint>

// OuterProductMean — fp16 mma.m16n8k16 (compute_103-safe), fully fused.
//
//  ln_wo  : blocks 0..255: LayerNorm + dual proj -> g_ah[s][m], g_bh[s][n] (fp16)
//           blocks 256..287: g_wo16 = fp16(wo)
//  fused  : per CTA (4 i x 8 j = 32 pairs):
//    stage: repack g_ah/g_bh -> SMEM [m][k]/[n][k] fp16 (k-contiguous, padded)
//    phase1: o[128 (i,c)][256 (j,d)] = sum_s a*b   (mma fp16, K=128)
//    stage o -> Os[p=32][k2=1024] fp16 (row-major, padded)
//    phase2: Z[32][128 z] = Os * wo^T (K=1024, 8 cp.async chunks of 128,
//            4-way k-split + SMEM reduction)

#define S_DIM 128
#define R_DIM 256
#define CM    256
#define CC    32
#define CZ    128
#define MDIM  (R_DIM * CC)          // 8192

__device__ __half g_ah[(size_t)S_DIM * MDIM];   // 2 MB [s][m]
__device__ __half g_bh[(size_t)S_DIM * MDIM];   // 2 MB [s][n]
__device__ __half g_wo16[(size_t)CZ * CC * CC]; // 256 KB [z][k2]

// ---------------------------------------------------------------- helpers
__device__ __forceinline__ uint32_t su32(const void* p) {
    uint32_t a;
    asm("{ .reg .u64 t; cvta.to.shared.u64 t, %1; cvt.u32.u64 %0, t; }"
        : "=r"(a) : "l"(p));
    return a;
}
__device__ __forceinline__ void cp16(void* dst_smem, const void* src) {
    asm volatile("cp.async.cg.shared.global [%0], [%1], 16;"
                 :: "r"(su32(dst_smem)), "l"(src));
}
__device__ __forceinline__ void cp_commit() {
    asm volatile("cp.async.commit_group;" ::: "memory");
}
template <int N>
__device__ __forceinline__ void cp_wait() {
    asm volatile("cp.async.wait_group %0;" :: "n"(N) : "memory");
}

// D(16x8,f32) += A(16x16,f16 row) * B(16x8,f16 col)
__device__ __forceinline__ void mma16(float* d, const uint32_t* a, uint32_t b0, uint32_t b1) {
    asm volatile(
        "mma.sync.aligned.m16n8k16.row.col.f32.f16.f16.f32 "
        "{%0,%1,%2,%3}, {%4,%5,%6,%7}, {%8,%9}, {%0,%1,%2,%3};"
        : "+f"(d[0]), "+f"(d[1]), "+f"(d[2]), "+f"(d[3])
        : "r"(a[0]), "r"(a[1]), "r"(a[2]), "r"(a[3]), "r"(b0), "r"(b1));
}

__device__ __forceinline__ uint32_t h2bits(__half2 h) {
    return *reinterpret_cast<uint32_t*>(&h);
}

// ---------------------------------------------------------------- ln + proj (+ wo convert)
#define LN_STRIDE 264
#define LN_SMEM ((64 + 32) * LN_STRIDE * 4)

__global__ __launch_bounds__(256, 1)
void ln_wo_kernel(const float* __restrict__ m,
                  const float* __restrict__ ln_w, const float* __restrict__ ln_b,
                  const float* __restrict__ w1, const float* __restrict__ b1,
                  const float* __restrict__ w2, const float* __restrict__ b2,
                  const float* __restrict__ wo) {
    if (blockIdx.x >= 2 * S_DIM) {           // wo -> fp16 (32 blocks)
        const int base = ((blockIdx.x - 2 * S_DIM) * 256 + threadIdx.x) * 16;
        #pragma unroll
        for (int t = 0; t < 4; t++) {
            const float4 v = *(const float4*)&wo[base + 4 * t];
            uint2 u;
            u.x = h2bits(__floats2half2_rn(v.x, v.y));
            u.y = h2bits(__floats2half2_rn(v.z, v.w));
            *(uint2*)&g_wo16[base + 4 * t] = u;
        }
        return;
    }

    extern __shared__ __align__(16) float sm_[];
    float* ws = sm_;                     // [64][264]
    float* xs = sm_ + 64 * LN_STRIDE;    // [32][264]

    const int s = blockIdx.x >> 1;
    const int half = blockIdx.x & 1;
    const int tid = threadIdx.x, w = tid >> 5, lane = tid & 31;

    for (int idx = tid; idx < 64 * 64; idx += 256) {
        const int row = idx >> 6, k4 = idx & 63;
        const float* src = (row < 32) ? (w1 + (size_t)row * CM)
                                      : (w2 + (size_t)(row - 32) * CM);
        *(float4*)(ws + row * LN_STRIDE + k4 * 4) = *(const float4*)(src + k4 * 4);
    }

    const float4 lw0 = ((const float4*)ln_w)[lane], lw1 = ((const float4*)ln_w)[lane + 32];
    const float4 lb0 = ((const float4*)ln_b)[lane], lb1 = ((const float4*)ln_b)[lane + 32];

    const int o0 = (tid >> 3) * 2, r0 = tid & 7;
    const float bias0 = (o0 < 32) ? b1[o0] : b2[o0 - 32];
    const float bias1 = (o0 < 32) ? b1[o0 + 1] : b2[o0 + 1 - 32];

    for (int b0r = half * 128; b0r < half * 128 + 128; b0r += 32) {
        __syncthreads();
        #pragma unroll
        for (int p = 0; p < 4; p++) {
            const int r = p * 8 + w;
            const float* rowp = m + ((size_t)s * R_DIM + (b0r + r)) * CM;
            const float4 v0 = ((const float4*)rowp)[lane];
            const float4 v1 = ((const float4*)rowp)[lane + 32];
            float sum = v0.x + v0.y + v0.z + v0.w + v1.x + v1.y + v1.z + v1.w;
            #pragma unroll
            for (int o = 16; o; o >>= 1) sum += __shfl_xor_sync(~0u, sum, o);
            const float mu = sum * (1.0f / CM);
            const float d0 = v0.x - mu, d1 = v0.y - mu, d2 = v0.z - mu, d3 = v0.w - mu;
            const float d4 = v1.x - mu, d5 = v1.y - mu, d6 = v1.z - mu, d7 = v1.w - mu;
            float vs = d0*d0 + d1*d1 + d2*d2 + d3*d3 + d4*d4 + d5*d5 + d6*d6 + d7*d7;
            #pragma unroll
            for (int o = 16; o; o >>= 1) vs += __shfl_xor_sync(~0u, vs, o);
            const float rstd = rsqrtf(vs * (1.0f / CM) + 1e-5f);
            float4 y0, y1;
            y0.x = d0 * rstd * lw0.x + lb0.x;  y0.y = d1 * rstd * lw0.y + lb0.y;
            y0.z = d2 * rstd * lw0.z + lb0.z;  y0.w = d3 * rstd * lw0.w + lb0.w;
            y1.x = d4 * rstd * lw1.x + lb1.x;  y1.y = d5 * rstd * lw1.y + lb1.y;
            y1.z = d6 * rstd * lw1.z + lb1.z;  y1.w = d7 * rstd * lw1.w + lb1.w;
            *(float4*)(xs + r * LN_STRIDE + 4 * lane)       = y0;
            *(float4*)(xs + r * LN_STRIDE + 128 + 4 * lane) = y1;
        }
        __syncthreads();

        float acc0[4] = {0.f, 0.f, 0.f, 0.f}, acc1[4] = {0.f, 0.f, 0.f, 0.f};
        const float* wr0 = ws + o0 * LN_STRIDE;
        const float* wr1 = wr0 + LN_STRIDE;
        #pragma unroll 8
        for (int k4 = 0; k4 < 64; k4++) {
            const float4 wa = *(const float4*)(wr0 + k4 * 4);
            const float4 wb = *(const float4*)(wr1 + k4 * 4);
            #pragma unroll
            for (int u = 0; u < 4; u++) {
                const float4 x = *(const float4*)(xs + (r0 + 8 * u) * LN_STRIDE + k4 * 4);
                acc0[u] = fmaf(wa.x, x.x, acc0[u]); acc0[u] = fmaf(wa.y, x.y, acc0[u]);
                acc0[u] = fmaf(wa.z, x.z, acc0[u]); acc0[u] = fmaf(wa.w, x.w, acc0[u]);
                acc1[u] = fmaf(wb.x, x.x, acc1[u]); acc1[u] = fmaf(wb.y, x.y, acc1[u]);
                acc1[u] = fmaf(wb.z, x.z, acc1[u]); acc1[u] = fmaf(wb.w, x.w, acc1[u]);
            }
        }
        #pragma unroll
        for (int u = 0; u < 4; u++) {
            const int i_abs = b0r + r0 + 8 * u;
            const __half2 v = __floats2half2_rn(acc0[u] + bias0, acc1[u] + bias1);
            if (o0 < 32)
                *(__half2*)&g_ah[(size_t)s * MDIM + i_abs * CC + o0] = v;
            else
                *(__half2*)&g_bh[(size_t)s * MDIM + i_abs * CC + (o0 - 32)] = v;
        }
    }
}

// ---------------------------------------------------------------- fused
// SMEM (uint32/h2 units):
//   sAh [128 m][68]  @0        (8704)      phase1 A, k-contiguous fp16
//   sBh [256 n][68]  @8704     (17408)     phase1 B
//   Os  [32 p][516]  @0        (16512)     phase2 A (reuses phase1 region)
//   wo bufs 2 x [128 z][68] @26112 (2x8704); reduction scratch reuses them.
#define OPS_STRIDE 68
#define SBH_OFF    8704
#define OS_STRIDE  516
#define WO_OFF     26112
#define WO_BUF     8704
#define FUSED_SMEM ((WO_OFF + 2 * WO_BUF) * 4)   // 174080 B

__device__ __forceinline__ void issue_wo(uint32_t* buf, int cc, int tid) {
    // chunk cc: g_wo16[z][cc*128 .. +127], 128 z rows x 256B = 2048 cp16
    #pragma unroll
    for (int t = 0; t < 4; t++) {
        const int idx = tid + t * 512;
        const int z = idx >> 4, q = idx & 15;
        cp16(buf + z * OPS_STRIDE + 4 * q,
             g_wo16 + (size_t)z * 1024 + cc * 128 + 8 * q);
    }
}

__global__ __launch_bounds__(512, 1)
void fused_kernel(const float* __restrict__ bo, float* __restrict__ out) {
    extern __shared__ __align__(16) uint32_t smu[];
    const int tid = threadIdx.x, w = tid >> 5, lane = tid & 31;
    const int g = lane >> 2, tg = lane & 3;
    const int i0 = blockIdx.x * 4, j0 = blockIdx.y * 8;
    const int m0 = i0 * CC, n0 = j0 * CC;

    uint32_t* wob0 = smu + WO_OFF;
    uint32_t* wob1 = smu + WO_OFF + WO_BUF;
    issue_wo(wob0, 0, tid); cp_commit();
    issue_wo(wob1, 1, tid); cp_commit();

    // ---- stage + repack: g_ah[s][m] -> sAh[m][k=s] (k-paired half2) ----
    #pragma unroll
    for (int it = 0; it < 4; it++) {
        const int idx = it * 512 + tid;
        const int sp = idx & 63, mq = idx >> 6;
        const uint2 r0 = *(const uint2*)&g_ah[(size_t)(2 * sp) * MDIM + m0 + 4 * mq];
        const uint2 r1 = *(const uint2*)&g_ah[(size_t)(2 * sp + 1) * MDIM + m0 + 4 * mq];
        const __half* h0 = (const __half*)&r0;
        const __half* h1 = (const __half*)&r1;
        #pragma unroll
        for (int t = 0; t < 4; t++)
            smu[(4 * mq + t) * OPS_STRIDE + sp] = h2bits(__halves2half2(h0[t], h1[t]));
    }
    #pragma unroll
    for (int it = 0; it < 8; it++) {
        const int idx = it * 512 + tid;
        const int sp = idx & 63, nq = idx >> 6;
        const uint2 r0 = *(const uint2*)&g_bh[(size_t)(2 * sp) * MDIM + n0 + 4 * nq];
        const uint2 r1 = *(const uint2*)&g_bh[(size_t)(2 * sp + 1) * MDIM + n0 + 4 * nq];
        const __half* h0 = (const __half*)&r0;
        const __half* h1 = (const __half*)&r1;
        #pragma unroll
        for (int t = 0; t < 4; t++)
            smu[SBH_OFF + (4 * nq + t) * OPS_STRIDE + sp] = h2bits(__halves2half2(h0[t], h1[t]));
    }
    __syncthreads();

    // ---- phase 1: o[128][256] = A * B^T over k=128 (8 k16 steps) ----
    const int mr = w >> 2, nc = w & 3;          // warp: 32m x 64n
    float acc[2][8][4];
    #pragma unroll
    for (int mt = 0; mt < 2; mt++)
        #pragma unroll
        for (int nt = 0; nt < 8; nt++)
            #pragma unroll
            for (int q = 0; q < 4; q++) acc[mt][nt][q] = 0.f;

    #pragma unroll
    for (int ks = 0; ks < 8; ks++) {
        uint32_t a[2][4];
        #pragma unroll
        for (int mt = 0; mt < 2; mt++) {
            const uint32_t* base = smu + (32 * mr + 16 * mt + g) * OPS_STRIDE + 8 * ks + tg;
            a[mt][0] = base[0];
            a[mt][1] = base[8 * OPS_STRIDE];
            a[mt][2] = base[4];
            a[mt][3] = base[8 * OPS_STRIDE + 4];
        }
        #pragma unroll
        for (int nt = 0; nt < 8; nt++) {
            const uint32_t* bb = smu + SBH_OFF + (64 * nc + 8 * nt + g) * OPS_STRIDE + 8 * ks + tg;
            const uint32_t b0 = bb[0], b1 = bb[4];
            mma16(acc[0][nt], a[0], b0, b1);
            mma16(acc[1][nt], a[1], b0, b1);
        }
    }
    __syncthreads();   // operands dead; region becomes Os

    // ---- stage o -> Os[p][k2] fp16 (row-major, stride 516 h2) ----
    #pragma unroll
    for (int mt = 0; mt < 2; mt++) {
        #pragma unroll
        for (int nt = 0; nt < 8; nt++) {
            const int p = 8 * mr + 2 * nc + (nt >> 2);
            const int d2 = (4 * nt & 15) + tg;           // (d>>1)
            #pragma unroll
            for (int rr = 0; rr < 2; rr++) {
                const int c = 16 * mt + 8 * rr + g;
                smu[p * OS_STRIDE + c * 16 + d2] =
                    h2bits(__floats2half2_rn(acc[mt][nt][2 * rr], acc[mt][nt][2 * rr + 1]));
            }
        }
    }

    // ---- phase 2: Z[32][128] = Os * wo^T, 8 chunks of 128 k2 ----
    const int kg = w >> 2, zg = w & 3;          // 4 k-groups x 4 z-groups(32 z)
    float zacc[2][4][4];
    #pragma unroll
    for (int mt = 0; mt < 2; mt++)
        #pragma unroll
        for (int nt = 0; nt < 4; nt++)
            #pragma unroll
            for (int q = 0; q < 4; q++) zacc[mt][nt][q] = 0.f;

    for (int cc = 0; cc < 8; cc++) {
        cp_wait<1>();
        __syncthreads();                        // chunk cc ready; Os visible (cc=0)
        const uint32_t* W = (cc & 1) ? wob1 : wob0;
        #pragma unroll
        for (int s2 = 0; s2 < 2; s2++) {
            const int kk = 2 * kg + s2;         // k16 step 0..7 within chunk
            const int kb = cc * 64 + kk * 8;    // h2 offset in Os rows
            uint32_t a[2][4];
            #pragma unroll
            for (int mt = 0; mt < 2; mt++) {
                const uint32_t* base = smu + (16 * mt + g) * OS_STRIDE + kb + tg;
                a[mt][0] = base[0];
                a[mt][1] = base[8 * OS_STRIDE];
                a[mt][2] = base[4];
                a[mt][3] = base[8 * OS_STRIDE + 4];
            }
            #pragma unroll
            for (int nt = 0; nt < 4; nt++) {
                const uint32_t* bb = W + (32 * zg + 8 * nt + g) * OPS_STRIDE + kk * 8 + tg;
                const uint32_t b0 = bb[0], b1 = bb[4];
                mma16(zacc[0][nt], a[0], b0, b1);
                mma16(zacc[1][nt], a[1], b0, b1);
            }
        }
        __syncthreads();                        // all warps done with this buffer
        if (cc + 2 < 8) issue_wo((cc & 1) ? wob1 : wob0, cc + 2, tid);
        cp_commit();
    }

    // ---- 4-way k reduction via SMEM (wo-buf region is dead) ----
    float* zf = &zacc[0][0][0];
    float* scr = (float*)(smu + WO_OFF);        // 2 blocks x 4224 fl
    const int slot = (zg * 32 + lane) * 33;
    if (kg >= 2) {
        float* dst = scr + (kg - 2) * 4224 + slot;
        #pragma unroll
        for (int x = 0; x < 32; x++) dst[x] = zf[x];
    }
    __syncthreads();
    if (kg < 2) {
        const float* src = scr + kg * 4224 + slot;
        #pragma unroll
        for (int x = 0; x < 32; x++) zf[x] += src[x];
    }
    __syncthreads();
    if (kg == 1) {
        float* dst = scr + slot;
        #pragma unroll
        for (int x = 0; x < 32; x++) dst[x] = zf[x];
    }
    __syncthreads();
    if (kg == 0) {
        const float* src = scr + slot;
        #pragma unroll
        for (int x = 0; x < 32; x++) zf[x] += src[x];

        // ---- epilogue ----
        #pragma unroll
        for (int mt = 0; mt < 2; mt++) {
            #pragma unroll
            for (int nt = 0; nt < 4; nt++) {
                const int zz = 32 * zg + 8 * nt + 2 * tg;
                const float2 bo2 = *(const float2*)&bo[zz];
                #pragma unroll
                for (int rr = 0; rr < 2; rr++) {
                    const int p = 16 * mt + 8 * rr + g;
                    const int i = i0 + (p >> 3), j = j0 + (p & 7);
                    float2 v;
                    v.x = (zacc[mt][nt][2 * rr + 0] + bo2.x) * (1.0f / S_DIM);
                    v.y = (zacc[mt][nt][2 * rr + 1] + bo2.y) * (1.0f / S_DIM);
                    *(float2*)&out[((size_t)i * R_DIM + j) * CZ + zz] = v;
                }
            }
        }
    }
}

// ---------------------------------------------------------------- launch
extern "C" void kernel_launch(void* const* d_in, const int* in_sizes, int n_in,
                              void* d_out, int out_size) {
    const float* m    = (const float*)d_in[0];
    const float* ln_w = (const float*)d_in[1];
    const float* ln_b = (const float*)d_in[2];
    const float* w1   = (const float*)d_in[3];
    const float* b1   = (const float*)d_in[4];
    const float* w2   = (const float*)d_in[5];
    const float* b2   = (const float*)d_in[6];
    const float* wo   = (const float*)d_in[7];
    const float* bo   = (const float*)d_in[8];
    float* out = (float*)d_out;

    cudaFuncSetAttribute(ln_wo_kernel, cudaFuncAttributeMaxDynamicSharedMemorySize, LN_SMEM);
    cudaFuncSetAttribute(fused_kernel, cudaFuncAttributeMaxDynamicSharedMemorySize, FUSED_SMEM);

    ln_wo_kernel<<<2 * S_DIM + 32, 256, LN_SMEM>>>(m, ln_w, ln_b, w1, b1, w2, b2, wo);
    fused_kernel<<<dim3(R_DIM / 4, R_DIM / 8), 512, FUSED_SMEM>>>(bo, out);
}